// round 2
// baseline (speedup 1.0000x reference)
#include <cuda_runtime.h>
#include <math.h>

// Problem dims
#define XD     2048
#define INDIM  512
#define OUTDIM 256
#define BATCH  64
#define TSTEPS 128
#define BT     (BATCH*TSTEPS)   // 8192
#define KH     (2*XD)           // 4096
#define NCTA   128              // persistent grid size (<=148 SMs, all resident)

// Scratch (static __device__ per allocation rules)
__device__ float g_H0[BT*XD];        // 64 MB: act(x @ W_in^T + b_in), all timesteps
__device__ float g_H4[BT*XD];        // 64 MB: h4 per timestep (feeds output GEMM)
__device__ float g_h1[BATCH*XD];
__device__ float g_h2[BATCH*XD];
__device__ float g_h3[BATCH*XD];
__device__ float g_part[8*BATCH*XD]; // split-K partials
__device__ float g_np_li[NCTA];      // per-half-row sumsq of h2 (li norm partials)
__device__ float g_np_bp[NCTA];      // per-half-row sumsq of h4 (bp norm partials)
__device__ unsigned g_cnt;           // grid barrier counter (monotonic)
__device__ unsigned g_sense;         // grid barrier release value

__device__ __forceinline__ float act_f(float h, int id) {
    switch (id) {
    case 0: return h > 0.f ? h : 0.f;                       // relu
    case 1: return 1.f / (1.f + expf(-h));                  // sigmoid
    case 2: return tanhf(h);                                // tanh
    case 3: return h >= 0.f ? h : 0.1f * h;                 // leaky_relu(0.1)
    default: {                                              // selu
        const float sc = 1.0507009873554805f;
        const float al = 1.6732632423543772f;
        return h > 0.f ? sc * h : sc * al * expm1f(h);
    }
    }
}

// ---------------------------------------------------------------------------
// Sense-reversal grid barrier (all NCTA CTAs co-resident).
// ---------------------------------------------------------------------------
__device__ __forceinline__ void gbar(unsigned &ls) {
    __syncthreads();
    if (threadIdx.x == 0) {
        ls++;
        __threadfence();                       // release our writes
        unsigned prev = atomicAdd(&g_cnt, 1u);
        if (prev == ls * NCTA - 1u) {
            atomicExch(&g_sense, ls);          // last arriver releases
        } else {
            while (*(volatile unsigned*)&g_sense < ls) { }
        }
        __threadfence();                       // acquire others' writes
    }
    __syncthreads();
}

// ---------------------------------------------------------------------------
// One split-K GEMM slice: partial[kb] = A_slice @ W_slice^T
//   C logical [64,2048], K=4096 = concat(A1[64,2048], A2[64,2048])
//   CTA (nt, kb): 128 n-cols at nt*128, 512 k at kb*512. Tile 64x128, BK=32.
//   A2 operand optionally scaled per-row by 1/max(sqrt(np[2m]+np[2m+1]),1e-12)
//   (fused l2-normalize of the recurrent carry), or zeroed (t==0).
// ---------------------------------------------------------------------------
__device__ __forceinline__ void gemm_phase(
    const float* __restrict__ A1, long lda1,
    const float* __restrict__ A2, long lda2,
    const float* __restrict__ np,   // norm partials for A2 rows (or null)
    int zero_a2,
    const float* __restrict__ W,    // [2048][4096] row-major
    int nt, int kb,
    float As[][64], float Ws[][128])
{
    const int t  = threadIdx.x;
    const int n0 = nt * 128;
    const int kstart = kb * 512;

    const float* A; long lda; int koff; float scale = 1.f;
    if (kstart < XD) { A = A1; lda = lda1; koff = kstart; }
    else             { A = A2; lda = lda2; koff = kstart - XD; }

    const int am  = t & 63;      // A: m row
    const int akq = t >> 6;      // A: k quarter -> 8 k's
    const int wn  = t & 127;     // W: n row
    const int wkq = t >> 7;      // W: k half -> 16 k's

    if (kstart >= XD) {
        if (zero_a2) { A = A1; lda = lda1; koff = 0; scale = 0.f; }
        else if (np) {
            const float s = np[2*am] + np[2*am+1];
            scale = 1.f / fmaxf(sqrtf(s), 1e-12f);
        }
    }

    const float* Aptr = A + (size_t)am * lda + koff + akq * 8;
    const float* Wptr = W + (size_t)(n0 + wn) * KH + kstart + wkq * 16;

    float4 pa0 = *(const float4*)(Aptr + 0);
    float4 pa1 = *(const float4*)(Aptr + 4);
    float4 pw0 = *(const float4*)(Wptr + 0);
    float4 pw1 = *(const float4*)(Wptr + 4);
    float4 pw2 = *(const float4*)(Wptr + 8);
    float4 pw3 = *(const float4*)(Wptr + 12);

    const int tx = t & 31;   // n group: cols tx*4..+3
    const int ty = t >> 5;   // m group: rows ty*8..+7

    float c[8][4];
    #pragma unroll
    for (int i = 0; i < 8; i++)
        #pragma unroll
        for (int j = 0; j < 4; j++) c[i][j] = 0.f;

    const int NC = 512 / 32;
    #pragma unroll 1
    for (int ch = 0; ch < NC; ch++) {
        __syncthreads();
        As[akq*8+0][am] = pa0.x * scale; As[akq*8+1][am] = pa0.y * scale;
        As[akq*8+2][am] = pa0.z * scale; As[akq*8+3][am] = pa0.w * scale;
        As[akq*8+4][am] = pa1.x * scale; As[akq*8+5][am] = pa1.y * scale;
        As[akq*8+6][am] = pa1.z * scale; As[akq*8+7][am] = pa1.w * scale;
        Ws[wkq*16+ 0][wn] = pw0.x; Ws[wkq*16+ 1][wn] = pw0.y;
        Ws[wkq*16+ 2][wn] = pw0.z; Ws[wkq*16+ 3][wn] = pw0.w;
        Ws[wkq*16+ 4][wn] = pw1.x; Ws[wkq*16+ 5][wn] = pw1.y;
        Ws[wkq*16+ 6][wn] = pw1.z; Ws[wkq*16+ 7][wn] = pw1.w;
        Ws[wkq*16+ 8][wn] = pw2.x; Ws[wkq*16+ 9][wn] = pw2.y;
        Ws[wkq*16+10][wn] = pw2.z; Ws[wkq*16+11][wn] = pw2.w;
        Ws[wkq*16+12][wn] = pw3.x; Ws[wkq*16+13][wn] = pw3.y;
        Ws[wkq*16+14][wn] = pw3.z; Ws[wkq*16+15][wn] = pw3.w;
        __syncthreads();

        if (ch + 1 < NC) {    // prefetch next chunk
            Aptr += 32; Wptr += 32;
            pa0 = *(const float4*)(Aptr + 0);
            pa1 = *(const float4*)(Aptr + 4);
            pw0 = *(const float4*)(Wptr + 0);
            pw1 = *(const float4*)(Wptr + 4);
            pw2 = *(const float4*)(Wptr + 8);
            pw3 = *(const float4*)(Wptr + 12);
        }

        #pragma unroll
        for (int kk = 0; kk < 32; kk++) {
            const float4 a0 = *(const float4*)&As[kk][ty*8];
            const float4 a1 = *(const float4*)&As[kk][ty*8+4];
            const float4 w  = *(const float4*)&Ws[kk][tx*4];
            const float av[8] = {a0.x,a0.y,a0.z,a0.w,a1.x,a1.y,a1.z,a1.w};
            const float wv[4] = {w.x,w.y,w.z,w.w};
            #pragma unroll
            for (int i = 0; i < 8; i++)
                #pragma unroll
                for (int j = 0; j < 4; j++)
                    c[i][j] = fmaf(av[i], wv[j], c[i][j]);
        }
    }

    float* P = g_part + (size_t)kb * BATCH * XD;
    #pragma unroll
    for (int i = 0; i < 8; i++) {
        const int m = ty * 8 + i;
        float4 v = make_float4(c[i][0], c[i][1], c[i][2], c[i][3]);
        *(float4*)&P[(size_t)m * XD + n0 + tx*4] = v;
    }
}

// ---------------------------------------------------------------------------
// Reduce split-K partials + bias + per-column activation; optional per-CTA
// (= per-half-row) sum-of-squares partial for fused l2-norm.
// CTA c covers the 1024 contiguous elements [c*1024, (c+1)*1024) of [64][2048].
// ---------------------------------------------------------------------------
__device__ __forceinline__ void reduce_phase(
    const float* __restrict__ bias,
    const int*   __restrict__ ids,
    float* __restrict__ dst, long ldc,
    float* __restrict__ np_out, int cta)
{
    const int idx = cta * 1024 + threadIdx.x * 4;
    const int m   = idx >> 11;
    const int n   = idx & (XD - 1);

    float4 s = *(const float4*)&g_part[idx];
    #pragma unroll
    for (int kb = 1; kb < 8; kb++) {
        const float4 p = *(const float4*)&g_part[(size_t)kb * BATCH * XD + idx];
        s.x += p.x; s.y += p.y; s.z += p.z; s.w += p.w;
    }
    const float4 b = *(const float4*)&bias[n];
    float4 o;
    o.x = act_f(s.x + b.x, ids[n+0]);
    o.y = act_f(s.y + b.y, ids[n+1]);
    o.z = act_f(s.z + b.z, ids[n+2]);
    o.w = act_f(s.w + b.w, ids[n+3]);
    *(float4*)&dst[(size_t)m * ldc + n] = o;

    if (np_out) {
        float q = fmaf(o.x, o.x, fmaf(o.y, o.y, fmaf(o.z, o.z, o.w * o.w)));
        #pragma unroll
        for (int off = 16; off; off >>= 1)
            q += __shfl_down_sync(0xffffffffu, q, off);
        __shared__ float sm[8];
        if ((threadIdx.x & 31) == 0) sm[threadIdx.x >> 5] = q;
        __syncthreads();
        if (threadIdx.x == 0) {
            float tot = 0.f;
            #pragma unroll
            for (int i = 0; i < 8; i++) tot += sm[i];
            np_out[cta] = tot;
        }
        __syncthreads();
    }
}

// ---------------------------------------------------------------------------
// Persistent kernel: the entire T=128 recurrent loop.
// ---------------------------------------------------------------------------
__global__ void __launch_bounds__(256, 1)
rnn_persistent(const float* __restrict__ W_h,
               const float* __restrict__ b_h,
               const int*   __restrict__ act_ids)
{
    __shared__ float As[32][64];
    __shared__ float Ws[32][128];

    const int cta = blockIdx.x;
    const int nt  = cta & 15;
    const int kb  = cta >> 4;
    const long ldH = (long)TSTEPS * XD;
    unsigned ls = 0;

    for (int t = 0; t < TSTEPS; t++) {
        const float* h0t  = g_H0 + (size_t)t * XD;
        const float* h4p  = g_H4 + (size_t)(t ? t - 1 : 0) * XD;

        // h1 = act1([h0_t, bp=norm(h4_{t-1})] @ Wh0^T + bh0)
        gemm_phase(h0t, ldH, h4p, ldH, g_np_bp, t == 0, W_h, nt, kb, As, Ws);
        gbar(ls);
        reduce_phase(b_h, act_ids + XD, g_h1, XD, nullptr, cta);
        gbar(ls);
        // h2 = act2([h1, li=norm(h2_{t-1})] @ Wh1^T + bh1)
        gemm_phase(g_h1, XD, g_h2, XD, g_np_li, t == 0,
                   W_h + (size_t)1 * XD * KH, nt, kb, As, Ws);
        gbar(ls);
        reduce_phase(b_h + XD, act_ids + 2*XD, g_h2, XD, g_np_li, cta);
        gbar(ls);
        // h3 = act3([h2, h1] @ Wh2^T + bh2)
        gemm_phase(g_h2, XD, g_h1, XD, nullptr, 0,
                   W_h + (size_t)2 * XD * KH, nt, kb, As, Ws);
        gbar(ls);
        reduce_phase(b_h + 2*XD, act_ids + 3*XD, g_h3, XD, nullptr, cta);
        gbar(ls);
        // h4 = act4([h3, h2] @ Wh3^T + bh3) -> stored at H4[:,t,:]
        gemm_phase(g_h3, XD, g_h2, XD, nullptr, 0,
                   W_h + (size_t)3 * XD * KH, nt, kb, As, Ws);
        gbar(ls);
        reduce_phase(b_h + 3*XD, act_ids + 4*XD, g_H4 + (size_t)t * XD, ldH,
                     g_np_bp, cta);
        gbar(ls);
    }
}

// ---------------------------------------------------------------------------
// Parallel GEMM with fused bias+activation (input projection & output head)
//   C[M,N] = act(A[M,K] @ W[N,K]^T + bias), tile 64x128, BK=32
// ---------------------------------------------------------------------------
__global__ void __launch_bounds__(256, 1)
gemm_big(const float* __restrict__ A, int lda,
         const float* __restrict__ W, int K,
         const float* __restrict__ bias,
         const int*   __restrict__ ids,
         float* __restrict__ C, int ldc)
{
    __shared__ float As[32][64];
    __shared__ float Ws[32][128];

    const int t  = threadIdx.x;
    const int n0 = blockIdx.x * 128;
    const int m0 = blockIdx.y * 64;

    const int am  = t & 63;
    const int akq = t >> 6;
    const int wn  = t & 127;
    const int wkq = t >> 7;

    const float* Aptr = A + (size_t)(m0 + am) * lda + akq * 8;
    const float* Wptr = W + (size_t)(n0 + wn) * K + wkq * 16;

    float4 pa0 = *(const float4*)(Aptr + 0);
    float4 pa1 = *(const float4*)(Aptr + 4);
    float4 pw0 = *(const float4*)(Wptr + 0);
    float4 pw1 = *(const float4*)(Wptr + 4);
    float4 pw2 = *(const float4*)(Wptr + 8);
    float4 pw3 = *(const float4*)(Wptr + 12);

    const int tx = t & 31;
    const int ty = t >> 5;

    float c[8][4];
    #pragma unroll
    for (int i = 0; i < 8; i++)
        #pragma unroll
        for (int j = 0; j < 4; j++) c[i][j] = 0.f;

    const int NC = K / 32;
    #pragma unroll 1
    for (int ch = 0; ch < NC; ch++) {
        __syncthreads();
        As[akq*8+0][am] = pa0.x; As[akq*8+1][am] = pa0.y;
        As[akq*8+2][am] = pa0.z; As[akq*8+3][am] = pa0.w;
        As[akq*8+4][am] = pa1.x; As[akq*8+5][am] = pa1.y;
        As[akq*8+6][am] = pa1.z; As[akq*8+7][am] = pa1.w;
        Ws[wkq*16+ 0][wn] = pw0.x; Ws[wkq*16+ 1][wn] = pw0.y;
        Ws[wkq*16+ 2][wn] = pw0.z; Ws[wkq*16+ 3][wn] = pw0.w;
        Ws[wkq*16+ 4][wn] = pw1.x; Ws[wkq*16+ 5][wn] = pw1.y;
        Ws[wkq*16+ 6][wn] = pw1.z; Ws[wkq*16+ 7][wn] = pw1.w;
        Ws[wkq*16+ 8][wn] = pw2.x; Ws[wkq*16+ 9][wn] = pw2.y;
        Ws[wkq*16+10][wn] = pw2.z; Ws[wkq*16+11][wn] = pw2.w;
        Ws[wkq*16+12][wn] = pw3.x; Ws[wkq*16+13][wn] = pw3.y;
        Ws[wkq*16+14][wn] = pw3.z; Ws[wkq*16+15][wn] = pw3.w;
        __syncthreads();

        if (ch + 1 < NC) {
            Aptr += 32; Wptr += 32;
            pa0 = *(const float4*)(Aptr + 0);
            pa1 = *(const float4*)(Aptr + 4);
            pw0 = *(const float4*)(Wptr + 0);
            pw1 = *(const float4*)(Wptr + 4);
            pw2 = *(const float4*)(Wptr + 8);
            pw3 = *(const float4*)(Wptr + 12);
        }

        #pragma unroll
        for (int kk = 0; kk < 32; kk++) {
            const float4 a0 = *(const float4*)&As[kk][ty*8];
            const float4 a1 = *(const float4*)&As[kk][ty*8+4];
            const float4 w  = *(const float4*)&Ws[kk][tx*4];
            const float av[8] = {a0.x,a0.y,a0.z,a0.w,a1.x,a1.y,a1.z,a1.w};
            const float wv[4] = {w.x,w.y,w.z,w.w};
            #pragma unroll
            for (int i = 0; i < 8; i++)
                #pragma unroll
                for (int j = 0; j < 4; j++)
                    c[i][j] = fmaf(av[i], wv[j], c[i][j]);
        }
    }

    #pragma unroll
    for (int i = 0; i < 8; i++) {
        const int m = m0 + ty * 8 + i;
        const int n = n0 + tx * 4;
        float4 o;
        o.x = act_f(c[i][0] + bias[n+0], ids[n+0]);
        o.y = act_f(c[i][1] + bias[n+1], ids[n+1]);
        o.z = act_f(c[i][2] + bias[n+2], ids[n+2]);
        o.w = act_f(c[i][3] + bias[n+3], ids[n+3]);
        *(float4*)&C[(size_t)m * ldc + n] = o;
    }
}

__global__ void reset_bar()
{
    if (threadIdx.x == 0) { g_cnt = 0u; g_sense = 0u; }
}

// ---------------------------------------------------------------------------
extern "C" void kernel_launch(void* const* d_in, const int* in_sizes, int n_in,
                              void* d_out, int out_size)
{
    const float* x        = (const float*)d_in[0];  // [64,128,512]
    const float* W_in     = (const float*)d_in[1];  // [2048,512]
    const float* b_in     = (const float*)d_in[2];  // [2048]
    const float* W_h      = (const float*)d_in[3];  // [4,2048,4096]
    const float* b_h      = (const float*)d_in[4];  // [4,2048]
    const float* W_out    = (const float*)d_in[5];  // [256,2048]
    const float* b_out    = (const float*)d_in[6];  // [256]
    const int*   act_ids  = (const int*)d_in[7];    // [5,2048]
    const int*   oact_ids = (const int*)d_in[8];    // [256]
    float*       out      = (float*)d_out;          // [64,128,256]

    float *H0, *H4;
    cudaGetSymbolAddress((void**)&H0, g_H0);
    cudaGetSymbolAddress((void**)&H4, g_H4);

    reset_bar<<<1, 32>>>();

    // H0 = act0(x @ W_in^T + b_in) for all (b,t) -- fully parallel
    gemm_big<<<dim3(XD/128, BT/64), 256>>>(x, INDIM, W_in, INDIM,
                                           b_in, act_ids, H0, XD);

    // Entire recurrent loop in one persistent kernel (tiny graph, no per-step
    // launches, fused l2-norm of the carries).
    rnn_persistent<<<NCTA, 256>>>(W_h, b_h, act_ids);

    // y = act_out(H4 @ W_out^T + b_out) for all (b,t) -- fully parallel
    gemm_big<<<dim3(OUTDIM/128, BT/64), 256>>>(H4, XD, W_out, XD,
                                               b_out, oact_ids, out, OUTDIM);
}

// round 4
// speedup vs baseline: 2.2808x; 2.2808x over previous
#include <cuda_runtime.h>
#include <cuda_bf16.h>
#include <math.h>
#include <stdint.h>

// Problem dims
#define XD     2048
#define INDIM  512
#define OUTDIM 256
#define BATCH  64
#define TSTEPS 128
#define BT     (BATCH*TSTEPS)   // 8192
#define KH     (2*XD)           // 4096
#define NCTA   128              // persistent grid (<=148 SMs, all resident)

// bf16 chunk-padded layout: chunk = 64 k-cols of one source, rows padded to
// 72 bf16 (144 B) for conflict-free fragment LDS.
// A chunk block (64 rows):  [hi 9216 B][lo 9216 B]  = 18432 B
// B chunk block (128 rows): [hi 18432 B][lo 18432 B] = 36864 B
#define ACB   18432
#define BCB   36864
#define ROWB  144
#define STAGE (ACB + BCB)       // 55296 B SMEM per pipeline stage

// Scratch (static __device__ per allocation rules)
__device__ float g_H4[BT*XD];                       // fp32 h4 (head GEMM input)
__device__ float g_part[8*BATCH*XD];                // split-K partials
__device__ float g_np_li[2][NCTA];                  // li norm partials (t parity)
__device__ float g_np_bp[2][NCTA];                  // bp norm partials
__device__ unsigned g_cnt;
__device__ unsigned g_sense;
__device__ __align__(16) unsigned char g_Wp[150994944];   // weights, split+laid out
__device__ __align__(16) unsigned char g_H0b[128*32*ACB]; // h0 bf16, per t
__device__ __align__(16) unsigned char g_H4b[128*32*ACB]; // h4 bf16, per t
__device__ __align__(16) unsigned char g_h1b[32*ACB];
__device__ __align__(16) unsigned char g_h2b[32*ACB];
__device__ __align__(16) unsigned char g_h3b[32*ACB];

// ---------------------------------------------------------------------------
// helpers
// ---------------------------------------------------------------------------
__device__ __forceinline__ uint32_t s2u(const void* p) {
    uint32_t a;
    asm("{ .reg .u64 t; cvta.to.shared.u64 t, %1; cvt.u32.u64 %0, t; }"
        : "=r"(a) : "l"(p));
    return a;
}

__device__ __forceinline__ void split2(float a, float b, uint32_t& h, uint32_t& l) {
    __nv_bfloat162 hp = __float22bfloat162_rn(make_float2(a, b));
    float2 hf = __bfloat1622float2(hp);
    __nv_bfloat162 lp = __float22bfloat162_rn(make_float2(a - hf.x, b - hf.y));
    h = *(uint32_t*)&hp;
    l = *(uint32_t*)&lp;
}

__device__ __forceinline__ void mbar_init(uint32_t a, uint32_t c) {
    asm volatile("mbarrier.init.shared.b64 [%0], %1;" :: "r"(a), "r"(c) : "memory");
}
__device__ __forceinline__ void mbar_expect(uint32_t a, uint32_t bytes) {
    asm volatile("mbarrier.arrive.expect_tx.shared.b64 _, [%0], %1;"
                 :: "r"(a), "r"(bytes) : "memory");
}
__device__ __forceinline__ void mbar_wait(uint32_t a, uint32_t parity) {
    asm volatile(
        "{\n\t.reg .pred P1;\n\t"
        "W_%=:\n\t"
        "mbarrier.try_wait.parity.acquire.cta.shared::cta.b64 P1, [%0], %1, 0x989680;\n\t"
        "@P1 bra.uni D_%=;\n\t"
        "bra.uni W_%=;\n\t"
        "D_%=:\n\t}"
        :: "r"(a), "r"(parity) : "memory");
}
__device__ __forceinline__ void bulk_g2s(uint32_t dst, const void* src,
                                         uint32_t bytes, uint32_t mbar) {
    asm volatile(
        "cp.async.bulk.shared::cluster.global.mbarrier::complete_tx::bytes "
        "[%0], [%1], %2, [%3];"
        :: "r"(dst), "l"(src), "r"(bytes), "r"(mbar) : "memory");
}
#define PROXY_FENCE()  asm volatile("fence.proxy.async.shared::cta;" ::: "memory")

#define MMA(c, a, b) \
    asm volatile("mma.sync.aligned.m16n8k16.row.col.f32.bf16.bf16.f32 " \
        "{%0,%1,%2,%3}, {%4,%5,%6,%7}, {%8,%9}, {%0,%1,%2,%3};" \
        : "+f"((c)[0]), "+f"((c)[1]), "+f"((c)[2]), "+f"((c)[3]) \
        : "r"((a)[0]), "r"((a)[1]), "r"((a)[2]), "r"((a)[3]), \
          "r"((b)[0]), "r"((b)[1]))

__device__ __forceinline__ float act_f(float h, int id) {
    switch (id) {
    case 0: return h > 0.f ? h : 0.f;
    case 1: return 1.f / (1.f + expf(-h));
    case 2: return tanhf(h);
    case 3: return h >= 0.f ? h : 0.1f * h;
    default: {
        const float sc = 1.0507009873554805f;
        const float al = 1.6732632423543772f;
        return h > 0.f ? sc * h : sc * al * expm1f(h);
    }
    }
}

// Sense-reversal grid barrier (all NCTA CTAs co-resident).
__device__ __forceinline__ void gbar(unsigned& ls) {
    __syncthreads();
    if (threadIdx.x == 0) {
        ls++;
        __threadfence();
        unsigned prev = atomicAdd(&g_cnt, 1u);
        if (prev == ls * NCTA - 1u) {
            atomicExch(&g_sense, ls);
        } else {
            while (*(volatile unsigned*)&g_sense < ls) { }
        }
        __threadfence();
    }
    __syncthreads();
}

// ---------------------------------------------------------------------------
// Reduce split-K partials + bias + activation. kb>=4 partials optionally
// scaled per-row by the fused l2-norm of the recurrent carry (linearity:
// (s*a)@W = s*(a@W)). Writes bf16 hi/lo chunk layout (+ optional fp32 dst,
// + optional norm partials for the NEXT step).
// ---------------------------------------------------------------------------
__device__ __forceinline__ void reduce_phase(
    const float* __restrict__ bias,
    const int*   __restrict__ ids,
    float* __restrict__ dst32, long ldc,
    unsigned char* __restrict__ dstb,
    const float* __restrict__ npr, int zr,
    float* __restrict__ npw, int cta)
{
    const int idx = cta * 1024 + threadIdx.x * 4;
    const int m   = idx >> 11;
    const int n   = idx & (XD - 1);

    float4 lo4 = *(const float4*)&g_part[idx];
    #pragma unroll
    for (int kb = 1; kb < 4; kb++) {
        const float4 p = *(const float4*)&g_part[(size_t)kb * BATCH * XD + idx];
        lo4.x += p.x; lo4.y += p.y; lo4.z += p.z; lo4.w += p.w;
    }
    float4 hi4 = *(const float4*)&g_part[(size_t)4 * BATCH * XD + idx];
    #pragma unroll
    for (int kb = 5; kb < 8; kb++) {
        const float4 p = *(const float4*)&g_part[(size_t)kb * BATCH * XD + idx];
        hi4.x += p.x; hi4.y += p.y; hi4.z += p.z; hi4.w += p.w;
    }
    float sm = 1.f;
    if (npr) {
        if (zr) sm = 0.f;
        else {
            const float ss = npr[2*m] + npr[2*m + 1];
            sm = 1.f / fmaxf(sqrtf(ss), 1e-12f);
        }
    }
    const float4 b = *(const float4*)&bias[n];
    float4 o;
    o.x = act_f(fmaf(sm, hi4.x, lo4.x) + b.x, ids[n+0]);
    o.y = act_f(fmaf(sm, hi4.y, lo4.y) + b.y, ids[n+1]);
    o.z = act_f(fmaf(sm, hi4.z, lo4.z) + b.z, ids[n+2]);
    o.w = act_f(fmaf(sm, hi4.w, lo4.w) + b.w, ids[n+3]);

    if (dst32) *(float4*)&dst32[(size_t)m * ldc + n] = o;

    // bf16 hi/lo chunk write
    {
        const int g = n >> 6, col = n & 63;
        uint32_t h0, l0, h1, l1;
        split2(o.x, o.y, h0, l0);
        split2(o.z, o.w, h1, l1);
        unsigned char* base = dstb + (size_t)g * ACB + m * ROWB + col * 2;
        *(uint2*)base          = make_uint2(h0, h1);
        *(uint2*)(base + 9216) = make_uint2(l0, l1);
    }

    if (npw) {
        float q = fmaf(o.x, o.x, fmaf(o.y, o.y, fmaf(o.z, o.z, o.w * o.w)));
        #pragma unroll
        for (int off = 16; off; off >>= 1)
            q += __shfl_down_sync(0xffffffffu, q, off);
        __shared__ float smq[8];
        if ((threadIdx.x & 31) == 0) smq[threadIdx.x >> 5] = q;
        __syncthreads();
        if (threadIdx.x == 0) {
            float tot = 0.f;
            #pragma unroll
            for (int i = 0; i < 8; i++) tot += smq[i];
            npw[cta] = tot;
        }
        __syncthreads();
    }
}

// ---------------------------------------------------------------------------
// Weight preprocessing: fp32 W_h -> bf16 hi/lo chunk-padded blocks.
// Block key = ((layer*16 + nt)*8 + kb)*8 + chunk, each BCB bytes.
// ---------------------------------------------------------------------------
__global__ void prep_w(const float* __restrict__ W)
{
    const long idx = (long)blockIdx.x * 256 + threadIdx.x;   // 4,194,304 threads
    const int  kg  = (int)(idx & 511);
    const long r   = idx >> 9;
    const int  n   = (int)(r & 2047);
    const int  l   = (int)(r >> 11);
    const int  k   = kg * 8;

    const float* s = W + (((size_t)l * XD + n) * KH + k);
    const float4 a = *(const float4*)s;
    const float4 b = *(const float4*)(s + 4);
    uint32_t hw[4], lw[4];
    split2(a.x, a.y, hw[0], lw[0]);
    split2(a.z, a.w, hw[1], lw[1]);
    split2(b.x, b.y, hw[2], lw[2]);
    split2(b.z, b.w, hw[3], lw[3]);

    const int nt = n >> 7, kb = k >> 9, c = (k >> 6) & 7;
    const int rw = n & 127, col = k & 63;
    size_t base = ((size_t)((l * 16 + nt) * 8 + kb) * 8 + c) * BCB
                + (size_t)rw * ROWB + col * 2;
    *(uint4*)(g_Wp + base)         = make_uint4(hw[0], hw[1], hw[2], hw[3]);
    *(uint4*)(g_Wp + base + ACB)   = make_uint4(lw[0], lw[1], lw[2], lw[3]);
}

// ---------------------------------------------------------------------------
// Persistent kernel: entire T=128 recurrent loop. Legacy mma.sync (HMMA)
// bf16 hi/lo 3-product GEMMs, cp.async.bulk staged, double buffered.
// CTA (nt, kb): C tile rows 0..63 x n [nt*128, +128), K-slice [kb*512, +512).
// ---------------------------------------------------------------------------
__global__ void __launch_bounds__(256, 1)
rnn_persistent(const float* __restrict__ b_h,
               const int*   __restrict__ act_ids)
{
    extern __shared__ char dsm[];
    __shared__ __align__(8) unsigned long long s_mbar[2];

    const int tid = threadIdx.x, wid = tid >> 5, lane = tid & 31;
    const int cta = blockIdx.x, nt = cta & 15, kb = cta >> 4;

    // 128-align the stage region
    const uint32_t raw = s2u(dsm);
    const uint32_t Sa  = (raw + 127) & ~127u;
    char* R = dsm + (Sa - raw);
    const uint32_t mb[2] = { s2u(&s_mbar[0]), s2u(&s_mbar[1]) };

    if (tid == 0) { mbar_init(mb[0], 1); mbar_init(mb[1], 1); }
    __syncthreads();

    int ph2[2] = { 0, 0 };     // stage mbarrier parities
    unsigned ls = 0;

    // fragment geometry
    const int g  = lane >> 2, i4 = lane & 3;
    const int wm = (wid >> 2) * 32;          // warp m origin (0 / 32)
    const int wn = (wid & 3) * 32;           // warp n origin (0..96)
    const int aro = (wm + g) * ROWB + i4 * 4;
    const int bro = (wn + g) * ROWB + i4 * 4;

    for (int t = 0; t < TSTEPS; t++) {
        #pragma unroll 1
        for (int phn = 0; phn < 4; phn++) {
            // phase sources / sinks
            const unsigned char *A1b, *A2b;
            const float* bias; const int* ids;
            float* dst32 = nullptr; long ldc = XD;
            unsigned char* dstb;
            const float* npr = nullptr; float* npw = nullptr; int zr = 0;
            if (phn == 0) {
                A1b = g_H0b + (size_t)t * 32 * ACB;
                A2b = g_H4b + (size_t)(t ? t - 1 : 0) * 32 * ACB;
                npr = g_np_bp[(t + 1) & 1]; zr = (t == 0);
                bias = b_h;        ids = act_ids + XD;     dstb = g_h1b;
            } else if (phn == 1) {
                A1b = g_h1b; A2b = g_h2b;
                npr = g_np_li[(t + 1) & 1]; zr = (t == 0);
                npw = g_np_li[t & 1];
                bias = b_h + XD;   ids = act_ids + 2*XD;   dstb = g_h2b;
            } else if (phn == 2) {
                A1b = g_h2b; A2b = g_h1b;
                bias = b_h + 2*XD; ids = act_ids + 3*XD;   dstb = g_h3b;
            } else {
                A1b = g_h3b; A2b = g_h2b;
                npw = g_np_bp[t & 1];
                bias = b_h + 3*XD; ids = act_ids + 4*XD;
                dstb = g_H4b + (size_t)t * 32 * ACB;
                dst32 = g_H4 + (size_t)t * XD; ldc = (long)TSTEPS * XD;
            }

            const unsigned char* Asl = (kb < 4) ? A1b + (size_t)kb * 8 * ACB
                                                : A2b + (size_t)(kb - 4) * 8 * ACB;
            const unsigned char* Bbl =
                g_Wp + (size_t)((phn * 16 + nt) * 8 + kb) * 8 * BCB;

            auto issue = [&](int c) {
                const int s = c & 1;
                PROXY_FENCE();
                mbar_expect(mb[s], (uint32_t)STAGE);
                bulk_g2s(Sa + s * STAGE,       Asl + (size_t)c * ACB, ACB, mb[s]);
                bulk_g2s(Sa + s * STAGE + ACB, Bbl + (size_t)c * BCB, BCB, mb[s]);
            };
            if (tid == 0) { issue(0); issue(1); }

            float acc[2][4][4];
            #pragma unroll
            for (int mt = 0; mt < 2; mt++)
                #pragma unroll
                for (int n4 = 0; n4 < 4; n4++)
                    #pragma unroll
                    for (int j = 0; j < 4; j++) acc[mt][n4][j] = 0.f;

            #pragma unroll 1
            for (int c = 0; c < 8; c++) {
                const int s = c & 1;
                mbar_wait(mb[s], (uint32_t)ph2[s]); ph2[s] ^= 1;

                const char* Ah = R + s * STAGE;
                const char* Al = Ah + 9216;
                const char* Bh = R + s * STAGE + ACB;
                const char* Bl = Bh + ACB;

                #pragma unroll
                for (int ks = 0; ks < 4; ks++) {
                    const int kof = ks * 32;
                    uint32_t ah[2][4], al[2][4], bh[4][2], bl[4][2];
                    #pragma unroll
                    for (int mt = 0; mt < 2; mt++) {
                        const int o = aro + mt * 16 * ROWB + kof;
                        ah[mt][0] = *(const uint32_t*)(Ah + o);
                        ah[mt][1] = *(const uint32_t*)(Ah + o + 8 * ROWB);
                        ah[mt][2] = *(const uint32_t*)(Ah + o + 16);
                        ah[mt][3] = *(const uint32_t*)(Ah + o + 8 * ROWB + 16);
                        al[mt][0] = *(const uint32_t*)(Al + o);
                        al[mt][1] = *(const uint32_t*)(Al + o + 8 * ROWB);
                        al[mt][2] = *(const uint32_t*)(Al + o + 16);
                        al[mt][3] = *(const uint32_t*)(Al + o + 8 * ROWB + 16);
                    }
                    #pragma unroll
                    for (int n4 = 0; n4 < 4; n4++) {
                        const int o = bro + n4 * 8 * ROWB + kof;
                        bh[n4][0] = *(const uint32_t*)(Bh + o);
                        bh[n4][1] = *(const uint32_t*)(Bh + o + 16);
                        bl[n4][0] = *(const uint32_t*)(Bl + o);
                        bl[n4][1] = *(const uint32_t*)(Bl + o + 16);
                    }
                    #pragma unroll
                    for (int mt = 0; mt < 2; mt++)
                        #pragma unroll
                        for (int n4 = 0; n4 < 4; n4++) {
                            MMA(acc[mt][n4], ah[mt], bh[n4]);
                            MMA(acc[mt][n4], ah[mt], bl[n4]);
                            MMA(acc[mt][n4], al[mt], bh[n4]);
                        }
                }
                __syncthreads();
                if (c + 2 < 8 && tid == 0) issue(c + 2);
            }

            // epilogue: write split-K partials
            {
                float* P = g_part + (size_t)kb * BATCH * XD;
                #pragma unroll
                for (int mt = 0; mt < 2; mt++) {
                    const int m = wm + mt * 16 + g;
                    #pragma unroll
                    for (int n4 = 0; n4 < 4; n4++) {
                        const int col = nt * 128 + wn + n4 * 8 + i4 * 2;
                        *(float2*)&P[(size_t)m * XD + col] =
                            make_float2(acc[mt][n4][0], acc[mt][n4][1]);
                        *(float2*)&P[(size_t)(m + 8) * XD + col] =
                            make_float2(acc[mt][n4][2], acc[mt][n4][3]);
                    }
                }
            }

            gbar(ls);
            reduce_phase(bias, ids, dst32, ldc, dstb, npr, zr, npw, cta);
            gbar(ls);
        }
    }
}

// ---------------------------------------------------------------------------
// Parallel fp32 SIMT GEMM with fused bias+activation (edge GEMMs).
// If Cb != null, writes bf16 hi/lo chunk layout keyed by (t, chunk, b)
// (input projection -> g_H0b); else writes fp32 C (output head).
// ---------------------------------------------------------------------------
__global__ void __launch_bounds__(256, 1)
gemm_big(const float* __restrict__ A, int lda,
         const float* __restrict__ W, int K,
         const float* __restrict__ bias,
         const int*   __restrict__ ids,
         float* __restrict__ C, int ldc,
         unsigned char* __restrict__ Cb)
{
    __shared__ float As[32][64];
    __shared__ float Ws[32][128];

    const int t  = threadIdx.x;
    const int n0 = blockIdx.x * 128;
    const int m0 = blockIdx.y * 64;

    const int am  = t & 63;
    const int akq = t >> 6;
    const int wn  = t & 127;
    const int wkq = t >> 7;

    const float* Aptr = A + (size_t)(m0 + am) * lda + akq * 8;
    const float* Wptr = W + (size_t)(n0 + wn) * K + wkq * 16;

    float4 pa0 = *(const float4*)(Aptr + 0);
    float4 pa1 = *(const float4*)(Aptr + 4);
    float4 pw0 = *(const float4*)(Wptr + 0);
    float4 pw1 = *(const float4*)(Wptr + 4);
    float4 pw2 = *(const float4*)(Wptr + 8);
    float4 pw3 = *(const float4*)(Wptr + 12);

    const int tx = t & 31;
    const int ty = t >> 5;

    float c[8][4];
    #pragma unroll
    for (int i = 0; i < 8; i++)
        #pragma unroll
        for (int j = 0; j < 4; j++) c[i][j] = 0.f;

    const int NC = K / 32;
    #pragma unroll 1
    for (int ch = 0; ch < NC; ch++) {
        __syncthreads();
        As[akq*8+0][am] = pa0.x; As[akq*8+1][am] = pa0.y;
        As[akq*8+2][am] = pa0.z; As[akq*8+3][am] = pa0.w;
        As[akq*8+4][am] = pa1.x; As[akq*8+5][am] = pa1.y;
        As[akq*8+6][am] = pa1.z; As[akq*8+7][am] = pa1.w;
        Ws[wkq*16+ 0][wn] = pw0.x; Ws[wkq*16+ 1][wn] = pw0.y;
        Ws[wkq*16+ 2][wn] = pw0.z; Ws[wkq*16+ 3][wn] = pw0.w;
        Ws[wkq*16+ 4][wn] = pw1.x; Ws[wkq*16+ 5][wn] = pw1.y;
        Ws[wkq*16+ 6][wn] = pw1.z; Ws[wkq*16+ 7][wn] = pw1.w;
        Ws[wkq*16+ 8][wn] = pw2.x; Ws[wkq*16+ 9][wn] = pw2.y;
        Ws[wkq*16+10][wn] = pw2.z; Ws[wkq*16+11][wn] = pw2.w;
        Ws[wkq*16+12][wn] = pw3.x; Ws[wkq*16+13][wn] = pw3.y;
        Ws[wkq*16+14][wn] = pw3.z; Ws[wkq*16+15][wn] = pw3.w;
        __syncthreads();

        if (ch + 1 < NC) {
            Aptr += 32; Wptr += 32;
            pa0 = *(const float4*)(Aptr + 0);
            pa1 = *(const float4*)(Aptr + 4);
            pw0 = *(const float4*)(Wptr + 0);
            pw1 = *(const float4*)(Wptr + 4);
            pw2 = *(const float4*)(Wptr + 8);
            pw3 = *(const float4*)(Wptr + 12);
        }

        #pragma unroll
        for (int kk = 0; kk < 32; kk++) {
            const float4 a0 = *(const float4*)&As[kk][ty*8];
            const float4 a1 = *(const float4*)&As[kk][ty*8+4];
            const float4 w  = *(const float4*)&Ws[kk][tx*4];
            const float av[8] = {a0.x,a0.y,a0.z,a0.w,a1.x,a1.y,a1.z,a1.w};
            const float wv[4] = {w.x,w.y,w.z,w.w};
            #pragma unroll
            for (int i = 0; i < 8; i++)
                #pragma unroll
                for (int j = 0; j < 4; j++)
                    c[i][j] = fmaf(av[i], wv[j], c[i][j]);
        }
    }

    #pragma unroll
    for (int i = 0; i < 8; i++) {
        const int m = m0 + ty * 8 + i;
        const int n = n0 + tx * 4;
        float4 o;
        o.x = act_f(c[i][0] + bias[n+0], ids[n+0]);
        o.y = act_f(c[i][1] + bias[n+1], ids[n+1]);
        o.z = act_f(c[i][2] + bias[n+2], ids[n+2]);
        o.w = act_f(c[i][3] + bias[n+3], ids[n+3]);
        if (Cb) {
            const int tt = m & 127, bb = m >> 7;
            const int gch = n >> 6, col = n & 63;
            uint32_t h0, l0, h1, l1;
            split2(o.x, o.y, h0, l0);
            split2(o.z, o.w, h1, l1);
            unsigned char* base = Cb + ((size_t)tt * 32 + gch) * ACB
                                + bb * ROWB + col * 2;
            *(uint2*)base          = make_uint2(h0, h1);
            *(uint2*)(base + 9216) = make_uint2(l0, l1);
        } else {
            *(float4*)&C[(size_t)m * ldc + n] = o;
        }
    }
}

// Zero barrier state + the two carry buffers read (scaled by 0) at t=0.
__global__ void init_state()
{
    const int i = blockIdx.x * blockDim.x + threadIdx.x;   // 73728 threads
    if (i == 0) { g_cnt = 0u; g_sense = 0u; }
    const uint4 z = make_uint4(0, 0, 0, 0);
    if (i < 36864) {
        *(uint4*)(g_h2b + (size_t)i * 16) = z;
        *(uint4*)(g_H4b + (size_t)i * 16) = z;    // slice t=0
    }
}

// ---------------------------------------------------------------------------
extern "C" void kernel_launch(void* const* d_in, const int* in_sizes, int n_in,
                              void* d_out, int out_size)
{
    const float* x        = (const float*)d_in[0];  // [64,128,512]
    const float* W_in     = (const float*)d_in[1];  // [2048,512]
    const float* b_in     = (const float*)d_in[2];  // [2048]
    const float* W_h      = (const float*)d_in[3];  // [4,2048,4096]
    const float* b_h      = (const float*)d_in[4];  // [4,2048]
    const float* W_out    = (const float*)d_in[5];  // [256,2048]
    const float* b_out    = (const float*)d_in[6];  // [256]
    const int*   act_ids  = (const int*)d_in[7];    // [5,2048]
    const int*   oact_ids = (const int*)d_in[8];    // [256]
    float*       out      = (float*)d_out;          // [64,128,256]

    float *H4;
    unsigned char *H0b;
    cudaGetSymbolAddress((void**)&H4, g_H4);
    cudaGetSymbolAddress((void**)&H0b, g_H0b);

    cudaFuncSetAttribute(rnn_persistent,
                         cudaFuncAttributeMaxDynamicSharedMemorySize,
                         2 * STAGE + 128);

    init_state<<<288, 256>>>();

    // Pre-split/lay out weights (every call; deterministic).
    prep_w<<<16384, 256>>>(W_h);

    // H0 = act0(x @ W_in^T + b_in), written straight into bf16 chunk layout.
    gemm_big<<<dim3(XD/128, BT/64), 256>>>(x, INDIM, W_in, INDIM,
                                           b_in, act_ids, nullptr, 0, H0b);

    // Entire recurrent loop: persistent HMMA kernel.
    rnn_persistent<<<NCTA, 256, 2 * STAGE + 128>>>(b_h, act_ids);

    // y = act_out(H4 @ W_out^T + b_out)
    gemm_big<<<dim3(OUTDIM/128, BT/64), 256>>>(H4, XD, W_out, XD,
                                               b_out, oact_ids, out, OUTDIM,
                                               nullptr);
}

// round 5
// speedup vs baseline: 2.3899x; 1.0479x over previous
#include <cuda_runtime.h>
#include <cuda_bf16.h>
#include <math.h>
#include <stdint.h>

// Problem dims
#define XD     2048
#define INDIM  512
#define OUTDIM 256
#define BATCH  64
#define TSTEPS 128
#define BT     (BATCH*TSTEPS)   // 8192
#define KH     (2*XD)           // 4096
#define NCTA   128              // persistent grid (<=148 SMs, all resident)

// bf16 chunk-padded layout: chunk = 64 k-cols of one source, rows padded to
// 72 bf16 (144 B) — conflict-free for both LDS and LDSM.
// A chunk block (64 rows):  [hi 9216 B][lo 9216 B]  = 18432 B
// B chunk block (128 rows): [hi 18432 B][lo 18432 B] = 36864 B
#define ACB   18432
#define BCB   36864
#define ROWB  144
#define NPHASE (TSTEPS*4)       // 512
#define NCHUNK (NPHASE*8)       // 4096 global B chunks

// Scratch (static __device__ per allocation rules)
__device__ float g_H4[BT*XD];                       // fp32 h4 (head GEMM input)
__device__ float g_part[8*BATCH*XD];                // split-K partials
__device__ float g_np_li[2][NCTA];                  // li norm partials (t parity)
__device__ float g_np_bp[2][NCTA];                  // bp norm partials
__device__ unsigned g_cnt;
__device__ unsigned g_sense;
__device__ __align__(16) unsigned char g_Wp[150994944];   // weights, split+laid out
__device__ __align__(16) unsigned char g_H0b[128*32*ACB]; // h0 bf16, per t
__device__ __align__(16) unsigned char g_H4b[128*32*ACB]; // h4 bf16, per t
__device__ __align__(16) unsigned char g_h1b[32*ACB];
__device__ __align__(16) unsigned char g_h2b[32*ACB];
__device__ __align__(16) unsigned char g_h3b[32*ACB];

// ---------------------------------------------------------------------------
// helpers
// ---------------------------------------------------------------------------
__device__ __forceinline__ uint32_t s2u(const void* p) {
    uint32_t a;
    asm("{ .reg .u64 t; cvta.to.shared.u64 t, %1; cvt.u32.u64 %0, t; }"
        : "=r"(a) : "l"(p));
    return a;
}

__device__ __forceinline__ void split2(float a, float b, uint32_t& h, uint32_t& l) {
    __nv_bfloat162 hp = __float22bfloat162_rn(make_float2(a, b));
    float2 hf = __bfloat1622float2(hp);
    __nv_bfloat162 lp = __float22bfloat162_rn(make_float2(a - hf.x, b - hf.y));
    h = *(uint32_t*)&hp;
    l = *(uint32_t*)&lp;
}

__device__ __forceinline__ void mbar_init(uint32_t a, uint32_t c) {
    asm volatile("mbarrier.init.shared.b64 [%0], %1;" :: "r"(a), "r"(c) : "memory");
}
__device__ __forceinline__ void mbar_expect(uint32_t a, uint32_t bytes) {
    asm volatile("mbarrier.arrive.expect_tx.shared.b64 _, [%0], %1;"
                 :: "r"(a), "r"(bytes) : "memory");
}
__device__ __forceinline__ void mbar_wait(uint32_t a, uint32_t parity) {
    asm volatile(
        "{\n\t.reg .pred P1;\n\t"
        "W_%=:\n\t"
        "mbarrier.try_wait.parity.acquire.cta.shared::cta.b64 P1, [%0], %1, 0x989680;\n\t"
        "@P1 bra.uni D_%=;\n\t"
        "bra.uni W_%=;\n\t"
        "D_%=:\n\t}"
        :: "r"(a), "r"(parity) : "memory");
}
__device__ __forceinline__ void bulk_g2s(uint32_t dst, const void* src,
                                         uint32_t bytes, uint32_t mbar) {
    asm volatile(
        "cp.async.bulk.shared::cluster.global.mbarrier::complete_tx::bytes "
        "[%0], [%1], %2, [%3];"
        :: "r"(dst), "l"(src), "r"(bytes), "r"(mbar) : "memory");
}
__device__ __forceinline__ void ldsm4(uint32_t* r, uint32_t a) {
    asm volatile("ldmatrix.sync.aligned.m8n8.x4.shared.b16 {%0,%1,%2,%3}, [%4];"
        : "=r"(r[0]), "=r"(r[1]), "=r"(r[2]), "=r"(r[3]) : "r"(a));
}
#define PROXY_FENCE()  asm volatile("fence.proxy.async.shared::cta;" ::: "memory")

#define MMA(c, a, b) \
    asm volatile("mma.sync.aligned.m16n8k16.row.col.f32.bf16.bf16.f32 " \
        "{%0,%1,%2,%3}, {%4,%5,%6,%7}, {%8,%9}, {%0,%1,%2,%3};" \
        : "+f"((c)[0]), "+f"((c)[1]), "+f"((c)[2]), "+f"((c)[3]) \
        : "r"((a)[0]), "r"((a)[1]), "r"((a)[2]), "r"((a)[3]), \
          "r"((b)[0]), "r"((b)[1]))

__device__ __forceinline__ float act_f(float h, int id) {
    switch (id) {
    case 0: return h > 0.f ? h : 0.f;
    case 1: return 1.f / (1.f + expf(-h));
    case 2: return tanhf(h);
    case 3: return h >= 0.f ? h : 0.1f * h;
    default: {
        const float sc = 1.0507009873554805f;
        const float al = 1.6732632423543772f;
        return h > 0.f ? sc * h : sc * al * expm1f(h);
    }
    }
}

// Sense-reversal grid barrier (all NCTA CTAs co-resident).
__device__ __forceinline__ void gbar(unsigned& ls) {
    __syncthreads();
    if (threadIdx.x == 0) {
        ls++;
        __threadfence();
        unsigned prev = atomicAdd(&g_cnt, 1u);
        if (prev == ls * NCTA - 1u) {
            atomicExch(&g_sense, ls);
        } else {
            while (*(volatile unsigned*)&g_sense < ls) { }
        }
        __threadfence();
    }
    __syncthreads();
}

// ---------------------------------------------------------------------------
// Reduce split-K partials + bias + activation. kb>=4 partials optionally
// scaled per-row by the fused l2-norm of the recurrent carry (linearity).
// ---------------------------------------------------------------------------
__device__ __forceinline__ void reduce_phase(
    const float* __restrict__ bias,
    const int*   __restrict__ ids,
    float* __restrict__ dst32, long ldc,
    unsigned char* __restrict__ dstb,
    const float* __restrict__ npr, int zr,
    float* __restrict__ npw, int cta)
{
    const int idx = cta * 1024 + threadIdx.x * 4;
    const int m   = idx >> 11;
    const int n   = idx & (XD - 1);

    float4 lo4 = *(const float4*)&g_part[idx];
    #pragma unroll
    for (int kb = 1; kb < 4; kb++) {
        const float4 p = *(const float4*)&g_part[(size_t)kb * BATCH * XD + idx];
        lo4.x += p.x; lo4.y += p.y; lo4.z += p.z; lo4.w += p.w;
    }
    float4 hi4 = *(const float4*)&g_part[(size_t)4 * BATCH * XD + idx];
    #pragma unroll
    for (int kb = 5; kb < 8; kb++) {
        const float4 p = *(const float4*)&g_part[(size_t)kb * BATCH * XD + idx];
        hi4.x += p.x; hi4.y += p.y; hi4.z += p.z; hi4.w += p.w;
    }
    float sm = 1.f;
    if (npr) {
        if (zr) sm = 0.f;
        else {
            const float ss = npr[2*m] + npr[2*m + 1];
            sm = 1.f / fmaxf(sqrtf(ss), 1e-12f);
        }
    }
    const float4 b = *(const float4*)&bias[n];
    float4 o;
    o.x = act_f(fmaf(sm, hi4.x, lo4.x) + b.x, ids[n+0]);
    o.y = act_f(fmaf(sm, hi4.y, lo4.y) + b.y, ids[n+1]);
    o.z = act_f(fmaf(sm, hi4.z, lo4.z) + b.z, ids[n+2]);
    o.w = act_f(fmaf(sm, hi4.w, lo4.w) + b.w, ids[n+3]);

    if (dst32) *(float4*)&dst32[(size_t)m * ldc + n] = o;

    {
        const int g = n >> 6, col = n & 63;
        uint32_t h0, l0, h1, l1;
        split2(o.x, o.y, h0, l0);
        split2(o.z, o.w, h1, l1);
        unsigned char* base = dstb + (size_t)g * ACB + m * ROWB + col * 2;
        *(uint2*)base          = make_uint2(h0, h1);
        *(uint2*)(base + 9216) = make_uint2(l0, l1);
    }

    if (npw) {
        float q = fmaf(o.x, o.x, fmaf(o.y, o.y, fmaf(o.z, o.z, o.w * o.w)));
        #pragma unroll
        for (int off = 16; off; off >>= 1)
            q += __shfl_down_sync(0xffffffffu, q, off);
        __shared__ float smq[8];
        if ((threadIdx.x & 31) == 0) smq[threadIdx.x >> 5] = q;
        __syncthreads();
        if (threadIdx.x == 0) {
            float tot = 0.f;
            #pragma unroll
            for (int i = 0; i < 8; i++) tot += smq[i];
            npw[cta] = tot;
        }
        __syncthreads();
    }
}

// ---------------------------------------------------------------------------
// Weight preprocessing: fp32 W_h -> bf16 hi/lo chunk-padded blocks.
// ---------------------------------------------------------------------------
__global__ void prep_w(const float* __restrict__ W)
{
    const long idx = (long)blockIdx.x * 256 + threadIdx.x;
    const int  kg  = (int)(idx & 511);
    const long r   = idx >> 9;
    const int  n   = (int)(r & 2047);
    const int  l   = (int)(r >> 11);
    const int  k   = kg * 8;

    const float* s = W + (((size_t)l * XD + n) * KH + k);
    const float4 a = *(const float4*)s;
    const float4 b = *(const float4*)(s + 4);
    uint32_t hw[4], lw[4];
    split2(a.x, a.y, hw[0], lw[0]);
    split2(a.z, a.w, hw[1], lw[1]);
    split2(b.x, b.y, hw[2], lw[2]);
    split2(b.z, b.w, hw[3], lw[3]);

    const int nt = n >> 7, kb = k >> 9, c = (k >> 6) & 7;
    const int rw = n & 127, col = k & 63;
    size_t base = ((size_t)((l * 16 + nt) * 8 + kb) * 8 + c) * BCB
                + (size_t)rw * ROWB + col * 2;
    *(uint4*)(g_Wp + base)         = make_uint4(hw[0], hw[1], hw[2], hw[3]);
    *(uint4*)(g_Wp + base + ACB)   = make_uint4(lw[0], lw[1], lw[2], lw[3]);
}

// ---------------------------------------------------------------------------
// Persistent kernel. SMEM: [A phase buffer 8*ACB][B stage0][B stage1].
// B chunk stream runs on a global chunk counter, crossing phase barriers.
// ---------------------------------------------------------------------------
__global__ void __launch_bounds__(256, 1)
rnn_persistent(const float* __restrict__ b_h,
               const int*   __restrict__ act_ids)
{
    extern __shared__ char dsm[];
    __shared__ __align__(8) unsigned long long s_mbB[2];
    __shared__ __align__(8) unsigned long long s_mbA[2];

    const int tid = threadIdx.x, wid = tid >> 5, lane = tid & 31;
    const int cta = blockIdx.x, nt = cta & 15, kb = cta >> 4;

    const uint32_t raw = s2u(dsm);
    const uint32_t A0u = (raw + 127) & ~127u;
    const uint32_t B0u = A0u + 8 * ACB;
    const uint32_t mbB[2] = { s2u(&s_mbB[0]), s2u(&s_mbB[1]) };
    const uint32_t mbA[2] = { s2u(&s_mbA[0]), s2u(&s_mbA[1]) };

    if (tid == 0) {
        mbar_init(mbB[0], 1); mbar_init(mbB[1], 1);
        mbar_init(mbA[0], 1); mbar_init(mbA[1], 1);
        PROXY_FENCE();
    }
    __syncthreads();

    // B issue on global chunk index (phase = cg>>3; weights depend on phase&3)
    auto issueB = [&](long cg) {
        if (cg >= NCHUNK) return;
        const int s = (int)(cg & 1);
        const int p = (int)((cg >> 3) & 3);
        const int c = (int)(cg & 7);
        const unsigned char* src =
            g_Wp + ((size_t)((p * 16 + nt) * 8 + kb) * 8 + c) * BCB;
        mbar_expect(mbB[s], (uint32_t)BCB);
        bulk_g2s(B0u + s * BCB, src, (uint32_t)BCB, mbB[s]);
    };
    if (tid == 0) { issueB(0); issueB(1); }

    // fragment geometry
    const int g  = lane >> 2, i4 = lane & 3;
    const int wm = (wid >> 2) * 32;
    const int wn = (wid & 3) * 32;
    // ldmatrix lane offsets
    const int l15 = lane & 15, lk = lane >> 4;
    const uint32_t aoff0 = (uint32_t)((wm + l15) * ROWB + lk * 16);
    const uint32_t aoff1 = (uint32_t)((wm + 16 + l15) * ROWB + lk * 16);
    const int lr = lane & 7, ls8 = (lane >> 3) & 1;
    const uint32_t boff0 = (uint32_t)((wn + lk * 8 + lr) * ROWB + ls8 * 16);
    const uint32_t boff1 = (uint32_t)((wn + 16 + lk * 8 + lr) * ROWB + ls8 * 16);

    int phb[2] = { 0, 0 };
    unsigned ls = 0;

    for (int pidx = 0; pidx < NPHASE; pidx++) {
        const int t = pidx >> 2, phn = pidx & 3;
        const int pa = pidx & 1;

        // phase sources / sinks
        const unsigned char *A1b, *A2b;
        const float* bias; const int* ids;
        float* dst32 = nullptr; long ldc = XD;
        unsigned char* dstb;
        const float* npr = nullptr; float* npw = nullptr; int zr = 0;
        if (phn == 0) {
            A1b = g_H0b + (size_t)t * 32 * ACB;
            A2b = g_H4b + (size_t)(t ? t - 1 : 0) * 32 * ACB;
            npr = g_np_bp[(t + 1) & 1]; zr = (t == 0);
            bias = b_h;        ids = act_ids + XD;     dstb = g_h1b;
        } else if (phn == 1) {
            A1b = g_h1b; A2b = g_h2b;
            npr = g_np_li[(t + 1) & 1]; zr = (t == 0);
            npw = g_np_li[t & 1];
            bias = b_h + XD;   ids = act_ids + 2*XD;   dstb = g_h2b;
        } else if (phn == 2) {
            A1b = g_h2b; A2b = g_h1b;
            bias = b_h + 2*XD; ids = act_ids + 3*XD;   dstb = g_h3b;
        } else {
            A1b = g_h3b; A2b = g_h2b;
            npw = g_np_bp[t & 1];
            bias = b_h + 3*XD; ids = act_ids + 4*XD;
            dstb = g_H4b + (size_t)t * 32 * ACB;
            dst32 = g_H4 + (size_t)t * XD; ldc = (long)TSTEPS * XD;
        }

        const unsigned char* Asl = (kb < 4) ? A1b + (size_t)kb * 8 * ACB
                                            : A2b + (size_t)(kb - 4) * 8 * ACB;

        // Stage whole-phase A (chunk 0 first so compute starts early).
        if (tid == 0) {
            mbar_expect(mbA[0], (uint32_t)ACB);
            bulk_g2s(A0u, Asl, (uint32_t)ACB, mbA[0]);
            mbar_expect(mbA[1], (uint32_t)(7 * ACB));
            bulk_g2s(A0u + ACB, Asl + ACB, (uint32_t)(7 * ACB), mbA[1]);
        }

        float acc[2][4][4];
        #pragma unroll
        for (int mt = 0; mt < 2; mt++)
            #pragma unroll
            for (int n4 = 0; n4 < 4; n4++)
                #pragma unroll
                for (int j = 0; j < 4; j++) acc[mt][n4][j] = 0.f;

        const long cgb = (long)pidx * 8;
        #pragma unroll 1
        for (int c = 0; c < 8; c++) {
            const int s = c & 1;
            mbar_wait(mbB[s], (uint32_t)phb[s]); phb[s] ^= 1;
            if (c == 0) mbar_wait(mbA[0], (uint32_t)pa);
            if (c == 1) mbar_wait(mbA[1], (uint32_t)pa);

            const uint32_t bA = A0u + c * ACB;
            const uint32_t bB = B0u + s * BCB;

            #pragma unroll
            for (int ks = 0; ks < 4; ks++) {
                const uint32_t kof = ks * 32;
                uint32_t ah[2][4], al[2][4], bhp[2][4], blp[2][4];
                ldsm4(ah[0], bA + aoff0 + kof);
                ldsm4(ah[1], bA + aoff1 + kof);
                ldsm4(al[0], bA + 9216 + aoff0 + kof);
                ldsm4(al[1], bA + 9216 + aoff1 + kof);
                ldsm4(bhp[0], bB + boff0 + kof);
                ldsm4(bhp[1], bB + boff1 + kof);
                ldsm4(blp[0], bB + 18432 + boff0 + kof);
                ldsm4(blp[1], bB + 18432 + boff1 + kof);
                #pragma unroll
                for (int mt = 0; mt < 2; mt++)
                    #pragma unroll
                    for (int P = 0; P < 2; P++) {
                        MMA(acc[mt][2*P],   ah[mt], bhp[P] + 0);
                        MMA(acc[mt][2*P],   ah[mt], blp[P] + 0);
                        MMA(acc[mt][2*P],   al[mt], bhp[P] + 0);
                        MMA(acc[mt][2*P+1], ah[mt], bhp[P] + 2);
                        MMA(acc[mt][2*P+1], ah[mt], blp[P] + 2);
                        MMA(acc[mt][2*P+1], al[mt], bhp[P] + 2);
                    }
            }
            __syncthreads();
            if (tid == 0) issueB(cgb + c + 2);   // crosses into next phase
        }

        // epilogue: write split-K partials
        {
            float* P = g_part + (size_t)kb * BATCH * XD;
            #pragma unroll
            for (int mt = 0; mt < 2; mt++) {
                const int m = wm + mt * 16 + g;
                #pragma unroll
                for (int n4 = 0; n4 < 4; n4++) {
                    const int col = nt * 128 + wn + n4 * 8 + i4 * 2;
                    *(float2*)&P[(size_t)m * XD + col] =
                        make_float2(acc[mt][n4][0], acc[mt][n4][1]);
                    *(float2*)&P[(size_t)(m + 8) * XD + col] =
                        make_float2(acc[mt][n4][2], acc[mt][n4][3]);
                }
            }
        }

        gbar(ls);
        reduce_phase(bias, ids, dst32, ldc, dstb, npr, zr, npw, cta);
        gbar(ls);
    }
}

// ---------------------------------------------------------------------------
// Parallel fp32 SIMT GEMM with fused bias+activation (edge GEMMs).
// ---------------------------------------------------------------------------
__global__ void __launch_bounds__(256, 1)
gemm_big(const float* __restrict__ A, int lda,
         const float* __restrict__ W, int K,
         const float* __restrict__ bias,
         const int*   __restrict__ ids,
         float* __restrict__ C, int ldc,
         unsigned char* __restrict__ Cb)
{
    __shared__ float As[32][64];
    __shared__ float Ws[32][128];

    const int t  = threadIdx.x;
    const int n0 = blockIdx.x * 128;
    const int m0 = blockIdx.y * 64;

    const int am  = t & 63;
    const int akq = t >> 6;
    const int wn  = t & 127;
    const int wkq = t >> 7;

    const float* Aptr = A + (size_t)(m0 + am) * lda + akq * 8;
    const float* Wptr = W + (size_t)(n0 + wn) * K + wkq * 16;

    float4 pa0 = *(const float4*)(Aptr + 0);
    float4 pa1 = *(const float4*)(Aptr + 4);
    float4 pw0 = *(const float4*)(Wptr + 0);
    float4 pw1 = *(const float4*)(Wptr + 4);
    float4 pw2 = *(const float4*)(Wptr + 8);
    float4 pw3 = *(const float4*)(Wptr + 12);

    const int tx = t & 31;
    const int ty = t >> 5;

    float c[8][4];
    #pragma unroll
    for (int i = 0; i < 8; i++)
        #pragma unroll
        for (int j = 0; j < 4; j++) c[i][j] = 0.f;

    const int NC = K / 32;
    #pragma unroll 1
    for (int ch = 0; ch < NC; ch++) {
        __syncthreads();
        As[akq*8+0][am] = pa0.x; As[akq*8+1][am] = pa0.y;
        As[akq*8+2][am] = pa0.z; As[akq*8+3][am] = pa0.w;
        As[akq*8+4][am] = pa1.x; As[akq*8+5][am] = pa1.y;
        As[akq*8+6][am] = pa1.z; As[akq*8+7][am] = pa1.w;
        Ws[wkq*16+ 0][wn] = pw0.x; Ws[wkq*16+ 1][wn] = pw0.y;
        Ws[wkq*16+ 2][wn] = pw0.z; Ws[wkq*16+ 3][wn] = pw0.w;
        Ws[wkq*16+ 4][wn] = pw1.x; Ws[wkq*16+ 5][wn] = pw1.y;
        Ws[wkq*16+ 6][wn] = pw1.z; Ws[wkq*16+ 7][wn] = pw1.w;
        Ws[wkq*16+ 8][wn] = pw2.x; Ws[wkq*16+ 9][wn] = pw2.y;
        Ws[wkq*16+10][wn] = pw2.z; Ws[wkq*16+11][wn] = pw2.w;
        Ws[wkq*16+12][wn] = pw3.x; Ws[wkq*16+13][wn] = pw3.y;
        Ws[wkq*16+14][wn] = pw3.z; Ws[wkq*16+15][wn] = pw3.w;
        __syncthreads();

        if (ch + 1 < NC) {
            Aptr += 32; Wptr += 32;
            pa0 = *(const float4*)(Aptr + 0);
            pa1 = *(const float4*)(Aptr + 4);
            pw0 = *(const float4*)(Wptr + 0);
            pw1 = *(const float4*)(Wptr + 4);
            pw2 = *(const float4*)(Wptr + 8);
            pw3 = *(const float4*)(Wptr + 12);
        }

        #pragma unroll
        for (int kk = 0; kk < 32; kk++) {
            const float4 a0 = *(const float4*)&As[kk][ty*8];
            const float4 a1 = *(const float4*)&As[kk][ty*8+4];
            const float4 w  = *(const float4*)&Ws[kk][tx*4];
            const float av[8] = {a0.x,a0.y,a0.z,a0.w,a1.x,a1.y,a1.z,a1.w};
            const float wv[4] = {w.x,w.y,w.z,w.w};
            #pragma unroll
            for (int i = 0; i < 8; i++)
                #pragma unroll
                for (int j = 0; j < 4; j++)
                    c[i][j] = fmaf(av[i], wv[j], c[i][j]);
        }
    }

    #pragma unroll
    for (int i = 0; i < 8; i++) {
        const int m = m0 + ty * 8 + i;
        const int n = n0 + tx * 4;
        float4 o;
        o.x = act_f(c[i][0] + bias[n+0], ids[n+0]);
        o.y = act_f(c[i][1] + bias[n+1], ids[n+1]);
        o.z = act_f(c[i][2] + bias[n+2], ids[n+2]);
        o.w = act_f(c[i][3] + bias[n+3], ids[n+3]);
        if (Cb) {
            const int tt = m & 127, bb = m >> 7;
            const int gch = n >> 6, col = n & 63;
            uint32_t h0, l0, h1, l1;
            split2(o.x, o.y, h0, l0);
            split2(o.z, o.w, h1, l1);
            unsigned char* base = Cb + ((size_t)tt * 32 + gch) * ACB
                                + bb * ROWB + col * 2;
            *(uint2*)base          = make_uint2(h0, h1);
            *(uint2*)(base + 9216) = make_uint2(l0, l1);
        } else {
            *(float4*)&C[(size_t)m * ldc + n] = o;
        }
    }
}

// Zero barrier state + the carry buffers read (scaled by 0) at t=0.
__global__ void init_state()
{
    const int i = blockIdx.x * blockDim.x + threadIdx.x;
    if (i == 0) { g_cnt = 0u; g_sense = 0u; }
    const uint4 z = make_uint4(0, 0, 0, 0);
    if (i < 36864) {
        *(uint4*)(g_h2b + (size_t)i * 16) = z;
        *(uint4*)(g_H4b + (size_t)i * 16) = z;    // slice t=0
    }
}

// ---------------------------------------------------------------------------
extern "C" void kernel_launch(void* const* d_in, const int* in_sizes, int n_in,
                              void* d_out, int out_size)
{
    const float* x        = (const float*)d_in[0];  // [64,128,512]
    const float* W_in     = (const float*)d_in[1];  // [2048,512]
    const float* b_in     = (const float*)d_in[2];  // [2048]
    const float* W_h      = (const float*)d_in[3];  // [4,2048,4096]
    const float* b_h      = (const float*)d_in[4];  // [4,2048]
    const float* W_out    = (const float*)d_in[5];  // [256,2048]
    const float* b_out    = (const float*)d_in[6];  // [256]
    const int*   act_ids  = (const int*)d_in[7];    // [5,2048]
    const int*   oact_ids = (const int*)d_in[8];    // [256]
    float*       out      = (float*)d_out;          // [64,128,256]

    float *H4;
    unsigned char *H0b;
    cudaGetSymbolAddress((void**)&H4, g_H4);
    cudaGetSymbolAddress((void**)&H0b, g_H0b);

    const int smem = 8 * ACB + 2 * BCB + 128;       // 221312
    cudaFuncSetAttribute(rnn_persistent,
                         cudaFuncAttributeMaxDynamicSharedMemorySize, smem);

    init_state<<<288, 256>>>();
    prep_w<<<16384, 256>>>(W_h);

    // H0 = act0(x @ W_in^T + b_in), written straight into bf16 chunk layout.
    gemm_big<<<dim3(XD/128, BT/64), 256>>>(x, INDIM, W_in, INDIM,
                                           b_in, act_ids, nullptr, 0, H0b);

    // Entire recurrent loop: persistent HMMA kernel.
    rnn_persistent<<<NCTA, 256, smem>>>(b_h, act_ids);

    // y = act_out(H4 @ W_out^T + b_out)
    gemm_big<<<dim3(OUTDIM/128, BT/64), 256>>>(H4, XD, W_out, XD,
                                               b_out, oact_ids, out, OUTDIM,
                                               nullptr);
}